// round 7
// baseline (speedup 1.0000x reference)
#include <cuda_runtime.h>
#include <math.h>

#define B_   32
#define NPTS 2048
#define L_   256
#define BIGF 1e18f
#define EPSF 1e-6f

#define LAMBDA_E_SUM       10.0f
#define LAMBDA_HIT         20.0f
#define LAMBDA_CHAMFER     0.001f
#define LAMBDA_HIT_ENTROPY 0.1f

typedef unsigned long long ull;

// ---------------- device scratch (module-load zero-initialized) ------------
// inverted-order keys: larger key == smaller distance; 0 == +inf identity.
// combine resets keys to 0 after reading -> valid for every graph replay.
__device__ unsigned g_min1[B_ * NPTS];   // pred->tgt, low 11 bits = argmin idx
__device__ unsigned g_min2[B_ * NPTS];   // tgt->pred
__device__ float    g_part[512][6];      // race-free per-block partials
__device__ unsigned g_ticket;

// ---------------------------------------------------------------------------
__device__ __forceinline__ ull fma2(ull a, ull b, ull c) {
    ull d;
    asm("fma.rn.f32x2 %0, %1, %2, %3;" : "=l"(d) : "l"(a), "l"(b), "l"(c));
    return d;
}
__device__ __forceinline__ ull dup2(float x) {
    ull d;
    asm("mov.b64 %0, {%1, %1};" : "=l"(d) : "f"(x));
    return d;
}
__device__ __forceinline__ ull pk2(float a, float b) {
    ull d;
    asm("mov.b64 %0, {%1, %2};" : "=l"(d) : "f"(a), "f"(b));
    return d;
}
__device__ __forceinline__ float2 unpack2(ull v) {
    float2 r;
    asm("mov.b64 {%0, %1}, %2;" : "=f"(r.x), "=f"(r.y) : "l"(v));
    return r;
}
// smaller float -> larger unsigned key (monotone inverted)
__device__ __forceinline__ unsigned encM(float f) {
    unsigned u = __float_as_uint(f);
    return ~(u ^ ((unsigned)((int)u >> 31) | 0x80000000u));
}
__device__ __forceinline__ float decM(unsigned key, unsigned& raw) {
    unsigned enc = ~key;
    unsigned m = (enc & 0x80000000u) ? 0x80000000u : 0xFFFFFFFFu;
    raw = enc ^ m;
    return __uint_as_float(raw);
}

__device__ __forceinline__ float blockReduceSum(float v, float* sh) {
    const unsigned full = 0xffffffffu;
    #pragma unroll
    for (int o = 16; o > 0; o >>= 1) v += __shfl_down_sync(full, v, o);
    int w = threadIdx.x >> 5, l = threadIdx.x & 31;
    __syncthreads();
    if (l == 0) sh[w] = v;
    __syncthreads();
    if (threadIdx.x < 32) {
        v = (threadIdx.x < (blockDim.x >> 5)) ? sh[threadIdx.x] : 0.0f;
        #pragma unroll
        for (int o = 16; o > 0; o >>= 1) v += __shfl_down_sync(full, v, o);
    }
    return v;
}

// ---------------------------------------------------------------------------
// Chamfer: 512 blocks = one resident wave.
//   blk>>8: 0 = pass1 (reg=pred, shared=target+mask), 1 = pass2 (reg=tgt,
//           shared=pred). b=(blk>>3)&31, regtile=(blk>>2)&1, chunk=blk&3.
// Fill 8 KB shared (256 pairs) cooperatively, ONE barrier, 256 j iterations
// against 4 register points per thread (packed f32x2: 8 pairs per i-loop).
__global__ __launch_bounds__(256, 4) void chamfer_kernel(
    const float* __restrict__ preds, const float* __restrict__ target,
    const float* __restrict__ mask) {
    __shared__ ulonglong2 shA[256], shB[256];
    int blk = blockIdx.x, tid = threadIdx.x;
    bool isP1 = blk < 256;
    int w = blk & 255;
    int b = w >> 3, rt = (w >> 2) & 1, ch = w & 3;

    // ---- cooperative shared fill: 1 packed pair per thread ----
    {
        int m = ch * 512 + 2 * tid;
        if (isP1) {
            const float* tb = target + (size_t)b * 4 * NPTS;
            float x0 = tb[m],            x1 = tb[m + 1];
            float y0 = tb[NPTS + m],     y1 = tb[NPTS + m + 1];
            float z0 = tb[2 * NPTS + m], z1 = tb[2 * NPTS + m + 1];
            float mk0 = mask[b * NPTS + m], mk1 = mask[b * NPTS + m + 1];
            float w0 = x0 * x0 + y0 * y0 + z0 * z0 + (mk0 == 0.f ? BIGF : 0.f);
            float w1 = x1 * x1 + y1 * y1 + z1 * z1 + (mk1 == 0.f ? BIGF : 0.f);
            shA[tid] = make_ulonglong2(pk2(x0, x1), pk2(y0, y1));
            shB[tid] = make_ulonglong2(pk2(z0, z1), pk2(w0, w1));
        } else {
            const float* pb = preds + (size_t)b * 5 * NPTS;
            float x0 = pb[m],            x1 = pb[m + 1];
            float y0 = pb[NPTS + m],     y1 = pb[NPTS + m + 1];
            float z0 = pb[2 * NPTS + m], z1 = pb[2 * NPTS + m + 1];
            float pn0 = x0 * x0 + y0 * y0 + z0 * z0;
            float pn1 = x1 * x1 + y1 * y1 + z1 * z1;
            shA[tid] = make_ulonglong2(pk2(-2.f * x0, -2.f * x1),
                                       pk2(-2.f * y0, -2.f * y1));
            shB[tid] = make_ulonglong2(pk2(-2.f * z0, -2.f * z1),
                                       pk2(pn0, pn1));
        }
    }

    // ---- register points: 4 per thread ----
    ull cx[4], cy[4], cz[4];
    {
        const float* rb = isP1 ? preds + (size_t)b * 5 * NPTS
                               : target + (size_t)b * 4 * NPTS;
        float sgn = isP1 ? -2.f : 1.f;
        #pragma unroll
        for (int i = 0; i < 4; i++) {
            int n = rt * 1024 + i * 256 + tid;
            cx[i] = dup2(sgn * rb[n]);
            cy[i] = dup2(sgn * rb[NPTS + n]);
            cz[i] = dup2(sgn * rb[2 * NPTS + n]);
        }
    }
    float bl[4], bh[4];
    #pragma unroll
    for (int i = 0; i < 4; i++) { bl[i] = 3.4e38f; bh[i] = 3.4e38f; }

    __syncthreads();   // the only barrier

    if (isP1) {
        unsigned jlo = (unsigned)(ch * 512);
        #pragma unroll 4
        for (int j = 0; j < 256; j++) {
            ulonglong2 A = shA[j], Bv = shB[j];
            unsigned jhi = jlo | 1u;
            #pragma unroll
            for (int i = 0; i < 4; i++) {
                ull t = fma2(cz[i], Bv.x, Bv.y);
                t = fma2(cy[i], A.y, t);
                t = fma2(cx[i], A.x, t);
                float2 v = unpack2(t);
                unsigned elo = (__float_as_uint(v.x) & 0xFFFFF800u) | jlo;
                unsigned ehi = (__float_as_uint(v.y) & 0xFFFFF800u) | jhi;
                bl[i] = fminf(bl[i], __uint_as_float(elo));
                bh[i] = fminf(bh[i], __uint_as_float(ehi));
            }
            jlo += 2;
        }
        #pragma unroll
        for (int i = 0; i < 4; i++) {
            int gidx = b * NPTS + rt * 1024 + i * 256 + tid;
            atomicMax(&g_min1[gidx], encM(fminf(bl[i], bh[i])));
        }
    } else {
        #pragma unroll 4
        for (int j = 0; j < 256; j++) {
            ulonglong2 A = shA[j], Bv = shB[j];
            #pragma unroll
            for (int i = 0; i < 4; i++) {
                ull t = fma2(cz[i], Bv.x, Bv.y);
                t = fma2(cy[i], A.y, t);
                t = fma2(cx[i], A.x, t);
                float2 v = unpack2(t);
                bl[i] = fminf(bl[i], v.x);
                bh[i] = fminf(bh[i], v.y);
            }
        }
        #pragma unroll
        for (int i = 0; i < 4; i++) {
            int gidx = b * NPTS + rt * 1024 + i * 256 + tid;
            atomicMax(&g_min2[gidx], encM(fminf(bl[i], bh[i])));
        }
    }
}

// ---------------------------------------------------------------------------
// Combine + all cheap reductions + finalize. 512 blocks, 256 points each:
//   [0,256)  pred side: minD_pred, |dE|, entropy, nhp, teh, kld slice
//   [256,512) tgt side: minD_tgt*mask, nht
__global__ __launch_bounds__(256) void combine_kernel(
    const float* __restrict__ preds, const float* __restrict__ target,
    const float* __restrict__ mask,  const float* __restrict__ mu,
    const float* __restrict__ logvar, const float* __restrict__ e_init,
    const float* __restrict__ kl_weight, float* __restrict__ out, int out_size) {
    __shared__ float shr[8];
    __shared__ int s_last;
    int blk = blockIdx.x, tid = threadIdx.x;

    if (blk < 256) {
        int b = blk >> 3, seg = blk & 7;
        int n = seg * 256 + tid;
        int gidx = b * NPTS + n;
        const float* pb = preds + (size_t)b * 5 * NPTS;
        const float* tE = target + (size_t)b * 4 * NPTS + 3 * NPTS;

        unsigned raw;
        float best = decM(g_min1[gidx], raw);
        g_min1[gidx] = 0u;
        int idx = (int)(raw & 0x7FFu);
        float x = pb[n], y = pb[NPTS + n], z = pb[2 * NPTS + n];
        float pn = x * x + y * y + z * z;
        float md = fmaxf(pn + best, 0.f);
        float pE = pb[3 * NPTS + n], h = pb[4 * NPTS + n];
        float le = fabsf(pE - tE[idx]);
        float ent = -(h * __logf(h + EPSF) + (1.f - h) * __logf(1.f - h + EPSF));
        float nhp = h;
        float teh = pE * h;
        float kld = 0.f;
        if (tid < 32) {
            int ki = blk * 32 + tid;   // 256 blocks x 32 = 8192 = B_*L_
            float m_ = mu[ki], lv = logvar[ki];
            kld = 1.f + lv - m_ * m_ - __expf(lv);
        }
        md  = blockReduceSum(md, shr);
        le  = blockReduceSum(le, shr);
        ent = blockReduceSum(ent, shr);
        kld = blockReduceSum(kld, shr);
        nhp = blockReduceSum(nhp, shr);
        teh = blockReduceSum(teh, shr);
        if (tid == 0) {
            float* s = g_part[blk];
            s[0] = md; s[1] = le; s[2] = ent; s[3] = kld; s[4] = nhp; s[5] = teh;
        }
    } else {
        int w = blk - 256;
        int b = w >> 3, seg = w & 7;
        int m = seg * 256 + tid;
        int gidx = b * NPTS + m;
        const float* tb = target + (size_t)b * 4 * NPTS;

        unsigned raw;
        float best = decM(g_min2[gidx], raw);
        g_min2[gidx] = 0u;
        float x = tb[m], y = tb[NPTS + m], z = tb[2 * NPTS + m];
        float tn = x * x + y * y + z * z;
        float mk = mask[gidx];
        float s = fmaxf(tn + best, 0.f) * mk;
        float nht = mk;
        s   = blockReduceSum(s, shr);
        nht = blockReduceSum(nht, shr);
        if (tid == 0) {
            float* p = g_part[blk];
            p[0] = s; p[1] = nht;
        }
    }

    if (tid == 0) {
        __threadfence();
        unsigned t = atomicAdd(&g_ticket, 1u);
        s_last = (t == 511u);
    }
    __syncthreads();
    if (!s_last) return;

    // ---- last block: aggregate 512 slots + finalize ----
    float vMD = blockReduceSum(g_part[tid][0], shr);
    float vLE = blockReduceSum(g_part[tid][1], shr);
    float vEN = blockReduceSum(g_part[tid][2], shr);
    float vKL = blockReduceSum(g_part[tid][3], shr);
    float vS  = blockReduceSum(g_part[256 + tid][0], shr);
    float vNH = blockReduceSum(g_part[256 + tid][1], shr);

    float dh2 = 0.f, de2 = 0.f;
    if (tid < B_) {
        float nhp = 0.f, teh = 0.f, nht = 0.f;
        #pragma unroll
        for (int s2 = 0; s2 < 8; s2++) {
            nhp += g_part[tid * 8 + s2][4];
            teh += g_part[tid * 8 + s2][5];
            nht += g_part[256 + tid * 8 + s2][1];
        }
        float dh = nhp - nht;
        float de = teh - e_init[tid];
        dh2 = dh * dh; de2 = de * de;
    }
    if (tid < 32) {
        const unsigned full = 0xffffffffu;
        #pragma unroll
        for (int o = 16; o > 0; o >>= 1) {
            dh2 += __shfl_down_sync(full, dh2, o);
            de2 += __shfl_down_sync(full, de2, o);
        }
    }
    if (tid == 0) {
        float chamP = vMD / (float)(B_ * NPTS);
        float chamT = vS / vNH;
        float loss_chamf = (chamT + chamP) * LAMBDA_CHAMFER;
        float localE = vLE / (float)(B_ * NPTS);
        float ge   = LAMBDA_E_SUM * de2 / (float)B_;
        float hit  = LAMBDA_HIT   * dh2 / (float)B_;
        float entr = LAMBDA_HIT_ENTROPY * vEN / (float)(B_ * NPTS);
        float kl   = kl_weight[0] * (-0.5f * vKL / (float)B_);
        float total = loss_chamf + localE + kl + ge + hit + entr;

        if (out_size >= 6) {
            out[0] = total;
            out[1] = loss_chamf;
            out[2] = localE;
            out[3] = ge;
            out[4] = hit;
            out[5] = kl;
        } else if (out_size == 5) {
            out[0] = loss_chamf; out[1] = localE; out[2] = ge;
            out[3] = hit;        out[4] = kl;
        } else {
            out[0] = total;
        }
        g_ticket = 0u;   // reset for next graph replay
    }
}

// ---------------------------------------------------------------------------
extern "C" void kernel_launch(void* const* d_in, const int* in_sizes, int n_in,
                              void* d_out, int out_size) {
    const float* preds  = (const float*)d_in[0];
    const float* target = (const float*)d_in[1];
    const float* tmask  = (const float*)d_in[2];
    const float* mu     = (const float*)d_in[3];
    const float* logvar = (const float*)d_in[4];
    const float* e_init = (const float*)d_in[5];
    const float* klw    = (const float*)d_in[6];
    float* out = (float*)d_out;

    chamfer_kernel<<<512, 256>>>(preds, target, tmask);
    combine_kernel<<<512, 256>>>(preds, target, tmask, mu, logvar,
                                 e_init, klw, out, out_size);
}

// round 8
// speedup vs baseline: 1.0851x; 1.0851x over previous
#include <cuda_runtime.h>
#include <math.h>

#define B_   32
#define NPTS 2048
#define L_   256
#define BIGF 1e18f
#define EPSF 1e-6f

#define LAMBDA_E_SUM       10.0f
#define LAMBDA_HIT         20.0f
#define LAMBDA_CHAMFER     0.001f
#define LAMBDA_HIT_ENTROPY 0.1f

typedef unsigned long long ull;

// ---------------- device scratch (module-load zero-initialized) ------------
__device__ float4 g_predPA[B_ * NPTS / 2];  // {-2x0,-2x1,-2y0,-2y1}
__device__ float4 g_predPB[B_ * NPTS / 2];  // {-2z0,-2z1, pn0, pn1}
__device__ float4 g_tgtPA [B_ * NPTS / 2];  // {x0,x1,y0,y1}
__device__ float4 g_tgtPB [B_ * NPTS / 2];  // {z0,z1, w0, w1} w=tn+BIG*!mask
__device__ float4 g_predS[B_ * NPTS];       // {-2x,-2y,-2z, pn}
__device__ float4 g_tgtS [B_ * NPTS];       // {  x,  y,  z, tn}
// inverted-order keys: larger key == smaller distance; 0 == +inf identity.
// combine resets keys to 0 after reading -> valid on every graph replay.
__device__ unsigned g_min1[B_ * NPTS];      // pred->tgt, low 11 bits = idx
__device__ unsigned g_min2[B_ * NPTS];      // tgt->pred
__device__ float    g_part[256][6];         // race-free per-block partials
__device__ unsigned g_ticket;

// ---------------------------------------------------------------------------
__device__ __forceinline__ ull fma2(ull a, ull b, ull c) {
    ull d;
    asm("fma.rn.f32x2 %0, %1, %2, %3;" : "=l"(d) : "l"(a), "l"(b), "l"(c));
    return d;
}
__device__ __forceinline__ ull dup2(float x) {
    ull d;
    asm("mov.b64 %0, {%1, %1};" : "=l"(d) : "f"(x));
    return d;
}
__device__ __forceinline__ float2 unpack2(ull v) {
    float2 r;
    asm("mov.b64 {%0, %1}, %2;" : "=f"(r.x), "=f"(r.y) : "l"(v));
    return r;
}
// smaller float -> larger unsigned key (monotone inverted)
__device__ __forceinline__ unsigned encM(float f) {
    unsigned u = __float_as_uint(f);
    return ~(u ^ ((unsigned)((int)u >> 31) | 0x80000000u));
}
__device__ __forceinline__ float decM(unsigned key, unsigned& raw) {
    unsigned enc = ~key;
    unsigned m = (enc & 0x80000000u) ? 0x80000000u : 0xFFFFFFFFu;
    raw = enc ^ m;
    return __uint_as_float(raw);
}

__device__ __forceinline__ float blockReduceSum(float v, float* sh) {
    const unsigned full = 0xffffffffu;
    #pragma unroll
    for (int o = 16; o > 0; o >>= 1) v += __shfl_down_sync(full, v, o);
    int w = threadIdx.x >> 5, l = threadIdx.x & 31;
    __syncthreads();
    if (l == 0) sh[w] = v;
    __syncthreads();
    if (threadIdx.x < 32) {
        v = (threadIdx.x < (blockDim.x >> 5)) ? sh[threadIdx.x] : 0.0f;
        #pragma unroll
        for (int o = 16; o > 0; o >>= 1) v += __shfl_down_sync(full, v, o);
    }
    return v;
}

// ---------------------------------------------------------------------------
// Pure data transform: 256 blocks, no reductions, no MUFU.
//   [0,128)  pred side: b=blk>>2, seg=blk&3
//   [128,256) tgt side
__global__ __launch_bounds__(256) void prep_kernel(
    const float* __restrict__ preds, const float* __restrict__ target,
    const float* __restrict__ mask) {
    int blk = blockIdx.x, tid = threadIdx.x;

    if (blk < 128) {
        int b = blk >> 2, seg = blk & 3;
        int jp = seg * 256 + tid;
        int n = 2 * jp;
        const float* pb = preds + (size_t)b * 5 * NPTS;
        float2 x = *(const float2*)(pb + n);
        float2 y = *(const float2*)(pb + NPTS + n);
        float2 z = *(const float2*)(pb + 2 * NPTS + n);
        float pn0 = x.x * x.x + y.x * y.x + z.x * z.x;
        float pn1 = x.y * x.y + y.y * y.y + z.y * z.y;
        g_predPA[b * 1024 + jp] = make_float4(-2.f * x.x, -2.f * x.y, -2.f * y.x, -2.f * y.y);
        g_predPB[b * 1024 + jp] = make_float4(-2.f * z.x, -2.f * z.y, pn0, pn1);
        g_predS[b * NPTS + n]     = make_float4(-2.f * x.x, -2.f * y.x, -2.f * z.x, pn0);
        g_predS[b * NPTS + n + 1] = make_float4(-2.f * x.y, -2.f * y.y, -2.f * z.y, pn1);
    } else {
        int w = blk - 128;
        int b = w >> 2, seg = w & 3;
        int jp = seg * 256 + tid;
        int n = 2 * jp;
        const float* tb = target + (size_t)b * 4 * NPTS;
        float2 x = *(const float2*)(tb + n);
        float2 y = *(const float2*)(tb + NPTS + n);
        float2 z = *(const float2*)(tb + 2 * NPTS + n);
        float2 mk = *(const float2*)(mask + b * NPTS + n);
        float tn0 = x.x * x.x + y.x * y.x + z.x * z.x;
        float tn1 = x.y * x.y + y.y * y.y + z.y * z.y;
        g_tgtPA[b * 1024 + jp] = make_float4(x.x, x.y, y.x, y.y);
        g_tgtPB[b * 1024 + jp] = make_float4(z.x, z.y,
                                             tn0 + (mk.x == 0.f ? BIGF : 0.f),
                                             tn1 + (mk.y == 0.f ? BIGF : 0.f));
        g_tgtS[b * NPTS + n]     = make_float4(x.x, y.x, z.x, tn0);
        g_tgtS[b * NPTS + n + 1] = make_float4(x.y, y.y, z.y, tn1);
    }
}

// ---------------------------------------------------------------------------
// Chamfer (R4 measured-best core). 1024 blocks:
//   [0,512)   pass1: pred->tgt, argmin in low 11 mantissa bits
//   [512,1024) pass2: tgt->pred, plain min
// Each block: 2048 register points (8/thread) x one 128-point smem chunk.
__global__ __launch_bounds__(256, 2) void chamfer_kernel() {
    __shared__ ulonglong2 shA[64], shB[64];
    int blk = blockIdx.x, tid = threadIdx.x;
    bool isP1 = blk < 512;
    int w = isP1 ? blk : blk - 512;
    int b = w >> 4, chunk = w & 15;

    if (tid < 64) {
        const float4* PA = isP1 ? g_tgtPA : g_predPA;
        const float4* PB = isP1 ? g_tgtPB : g_predPB;
        float4 a = PA[b * 1024 + chunk * 64 + tid];
        float4 v = PB[b * 1024 + chunk * 64 + tid];
        shA[tid] = *(ulonglong2*)&a;
        shB[tid] = *(ulonglong2*)&v;
    }
    __syncthreads();

    if (isP1) {
        int pbase = b * NPTS + tid;
        ull ax2[8], ay2[8], az2[8];
        #pragma unroll
        for (int i = 0; i < 8; i++) {
            float4 p = g_predS[pbase + i * 256];
            ax2[i] = dup2(p.x); ay2[i] = dup2(p.y); az2[i] = dup2(p.z);
        }
        float bl[8], bh[8];
        #pragma unroll
        for (int i = 0; i < 8; i++) { bl[i] = 3.4e38f; bh[i] = 3.4e38f; }

        unsigned jlo = (unsigned)(chunk * 128);
        #pragma unroll 4
        for (int j = 0; j < 64; j++) {
            ulonglong2 A = shA[j], Bv = shB[j];
            unsigned jhi = jlo | 1u;
            #pragma unroll
            for (int i = 0; i < 8; i++) {
                ull t = fma2(az2[i], Bv.x, Bv.y);
                t = fma2(ay2[i], A.y, t);
                t = fma2(ax2[i], A.x, t);
                float2 v = unpack2(t);
                unsigned elo = (__float_as_uint(v.x) & 0xFFFFF800u) | jlo;
                unsigned ehi = (__float_as_uint(v.y) & 0xFFFFF800u) | jhi;
                bl[i] = fminf(bl[i], __uint_as_float(elo));
                bh[i] = fminf(bh[i], __uint_as_float(ehi));
            }
            jlo += 2;
        }
        #pragma unroll
        for (int i = 0; i < 8; i++)
            atomicMax(&g_min1[pbase + i * 256], encM(fminf(bl[i], bh[i])));
    } else {
        int tbase = b * NPTS + tid;
        ull tx2[8], ty2[8], tz2[8];
        #pragma unroll
        for (int i = 0; i < 8; i++) {
            float4 t = g_tgtS[tbase + i * 256];
            tx2[i] = dup2(t.x); ty2[i] = dup2(t.y); tz2[i] = dup2(t.z);
        }
        float bl[8], bh[8];
        #pragma unroll
        for (int i = 0; i < 8; i++) { bl[i] = 3.4e38f; bh[i] = 3.4e38f; }

        #pragma unroll 4
        for (int j = 0; j < 64; j++) {
            ulonglong2 A = shA[j], Bv = shB[j];
            #pragma unroll
            for (int i = 0; i < 8; i++) {
                ull t = fma2(tz2[i], Bv.x, Bv.y);
                t = fma2(ty2[i], A.y, t);
                t = fma2(tx2[i], A.x, t);
                float2 v = unpack2(t);
                bl[i] = fminf(bl[i], v.x);
                bh[i] = fminf(bh[i], v.y);
            }
        }
        #pragma unroll
        for (int i = 0; i < 8; i++)
            atomicMax(&g_min2[tbase + i * 256], encM(fminf(bl[i], bh[i])));
    }
}

// ---------------------------------------------------------------------------
// Combine: all reductions + finalize. 256 blocks, 512 points each:
//   [0,128)  pred side: minD_pred, |dE|, entropy, nhp, teh, kld slice
//   [128,256) tgt side: minD_tgt*mask, nht
__global__ __launch_bounds__(256) void combine_kernel(
    const float* __restrict__ preds, const float* __restrict__ target,
    const float* __restrict__ mask,  const float* __restrict__ mu,
    const float* __restrict__ logvar, const float* __restrict__ e_init,
    const float* __restrict__ kl_weight, float* __restrict__ out, int out_size) {
    __shared__ float shr[8];
    __shared__ int s_last;
    int blk = blockIdx.x, tid = threadIdx.x;

    if (blk < 128) {
        int b = blk >> 2, seg = blk & 3;
        const float* pb = preds + (size_t)b * 5 * NPTS;
        const float* tE = target + (size_t)b * 4 * NPTS + 3 * NPTS;
        float md = 0.f, le = 0.f, ent = 0.f, nhp = 0.f, teh = 0.f;
        #pragma unroll
        for (int r = 0; r < 2; r++) {
            int n = seg * 512 + r * 256 + tid;
            int gidx = b * NPTS + n;
            unsigned raw;
            float best = decM(g_min1[gidx], raw);
            g_min1[gidx] = 0u;
            int idx = (int)(raw & 0x7FFu);
            md += fmaxf(g_predS[gidx].w + best, 0.f);
            float pE = pb[3 * NPTS + n], h = pb[4 * NPTS + n];
            le += fabsf(pE - tE[idx]);
            ent += -(h * __logf(h + EPSF) + (1.f - h) * __logf(1.f - h + EPSF));
            nhp += h;
            teh += pE * h;
        }
        float kld = 0.f;
        if (tid < 64) {
            int ki = blk * 64 + tid;    // 128 blocks x 64 = 8192 = B_*L_
            float m_ = mu[ki], lv = logvar[ki];
            kld = 1.f + lv - m_ * m_ - __expf(lv);
        }
        md  = blockReduceSum(md, shr);
        le  = blockReduceSum(le, shr);
        ent = blockReduceSum(ent, shr);
        kld = blockReduceSum(kld, shr);
        nhp = blockReduceSum(nhp, shr);
        teh = blockReduceSum(teh, shr);
        if (tid == 0) {
            float* s = g_part[blk];
            s[0] = md; s[1] = le; s[2] = ent; s[3] = kld; s[4] = nhp; s[5] = teh;
        }
    } else {
        int w = blk - 128;
        int b = w >> 2, seg = w & 3;
        float s = 0.f, nht = 0.f;
        #pragma unroll
        for (int r = 0; r < 2; r++) {
            int m = seg * 512 + r * 256 + tid;
            int gidx = b * NPTS + m;
            unsigned raw;
            float best = decM(g_min2[gidx], raw);
            g_min2[gidx] = 0u;
            float mk = mask[gidx];
            s += fmaxf(g_tgtS[gidx].w + best, 0.f) * mk;
            nht += mk;
        }
        s   = blockReduceSum(s, shr);
        nht = blockReduceSum(nht, shr);
        if (tid == 0) {
            float* p = g_part[blk];
            p[0] = s; p[1] = nht;
        }
    }

    if (tid == 0) {
        __threadfence();
        unsigned t = atomicAdd(&g_ticket, 1u);
        s_last = (t == 255u);
    }
    __syncthreads();
    if (!s_last) return;

    // ---- last block: aggregate 256 slots + finalize ----
    float vMD = blockReduceSum(tid < 128 ? g_part[tid][0] : 0.f, shr);
    float vLE = blockReduceSum(tid < 128 ? g_part[tid][1] : 0.f, shr);
    float vEN = blockReduceSum(tid < 128 ? g_part[tid][2] : 0.f, shr);
    float vKL = blockReduceSum(tid < 128 ? g_part[tid][3] : 0.f, shr);
    float vS  = blockReduceSum(tid >= 128 ? g_part[tid][0] : 0.f, shr);
    float vNH = blockReduceSum(tid >= 128 ? g_part[tid][1] : 0.f, shr);

    float dh2 = 0.f, de2 = 0.f;
    if (tid < B_) {
        float nhp = 0.f, teh = 0.f, nht = 0.f;
        #pragma unroll
        for (int s2 = 0; s2 < 4; s2++) {
            nhp += g_part[4 * tid + s2][4];
            teh += g_part[4 * tid + s2][5];
            nht += g_part[128 + 4 * tid + s2][1];
        }
        float dh = nhp - nht;
        float de = teh - e_init[tid];
        dh2 = dh * dh; de2 = de * de;
    }
    if (tid < 32) {
        const unsigned full = 0xffffffffu;
        #pragma unroll
        for (int o = 16; o > 0; o >>= 1) {
            dh2 += __shfl_down_sync(full, dh2, o);
            de2 += __shfl_down_sync(full, de2, o);
        }
    }
    if (tid == 0) {
        float chamP = vMD / (float)(B_ * NPTS);
        float chamT = vS / vNH;
        float loss_chamf = (chamT + chamP) * LAMBDA_CHAMFER;
        float localE = vLE / (float)(B_ * NPTS);
        float ge   = LAMBDA_E_SUM * de2 / (float)B_;
        float hit  = LAMBDA_HIT   * dh2 / (float)B_;
        float entr = LAMBDA_HIT_ENTROPY * vEN / (float)(B_ * NPTS);
        float kl   = kl_weight[0] * (-0.5f * vKL / (float)B_);
        float total = loss_chamf + localE + kl + ge + hit + entr;

        if (out_size >= 6) {
            out[0] = total;
            out[1] = loss_chamf;
            out[2] = localE;
            out[3] = ge;
            out[4] = hit;
            out[5] = kl;
        } else if (out_size == 5) {
            out[0] = loss_chamf; out[1] = localE; out[2] = ge;
            out[3] = hit;        out[4] = kl;
        } else {
            out[0] = total;
        }
        g_ticket = 0u;   // reset for next graph replay
    }
}

// ---------------------------------------------------------------------------
extern "C" void kernel_launch(void* const* d_in, const int* in_sizes, int n_in,
                              void* d_out, int out_size) {
    const float* preds  = (const float*)d_in[0];
    const float* target = (const float*)d_in[1];
    const float* tmask  = (const float*)d_in[2];
    const float* mu     = (const float*)d_in[3];
    const float* logvar = (const float*)d_in[4];
    const float* e_init = (const float*)d_in[5];
    const float* klw    = (const float*)d_in[6];
    float* out = (float*)d_out;

    prep_kernel<<<256, 256>>>(preds, target, tmask);
    chamfer_kernel<<<1024, 256>>>();
    combine_kernel<<<256, 256>>>(preds, target, tmask, mu, logvar,
                                 e_init, klw, out, out_size);
}

// round 10
// speedup vs baseline: 1.0907x; 1.0052x over previous
#include <cuda_runtime.h>
#include <math.h>

#define B_   32
#define NPTS 2048
#define L_   256
#define BIGF 1e18f
#define EPSF 1e-6f

#define LAMBDA_E_SUM       10.0f
#define LAMBDA_HIT         20.0f
#define LAMBDA_CHAMFER     0.001f
#define LAMBDA_HIT_ENTROPY 0.1f

typedef unsigned long long ull;

// ---------------- device scratch (module-load zero-initialized) ------------
__device__ float4 g_predPA[B_ * NPTS / 2];  // {-2x0,-2x1,-2y0,-2y1}
__device__ float4 g_predPB[B_ * NPTS / 2];  // {-2z0,-2z1, pn0, pn1}
__device__ float4 g_tgtPA [B_ * NPTS / 2];  // {x0,x1,y0,y1}
__device__ float4 g_tgtPB [B_ * NPTS / 2];  // {z0,z1, w0, w1} w=tn+BIG*!mask
__device__ float4 g_predS[B_ * NPTS];       // {-2x,-2y,-2z, pn}
__device__ float4 g_tgtS [B_ * NPTS];       // {  x,  y,  z, tn}
// inverted-order keys: larger key == smaller distance; 0 == +inf identity.
// combine resets keys to 0 after reading -> valid on every graph replay.
__device__ unsigned g_min1[B_ * NPTS];      // pred->tgt, low 11 bits = idx
__device__ unsigned g_min2[B_ * NPTS];      // tgt->pred
// race-free partial slots
__device__ float g_prep[256][4];  // blk<128: ent,kld,nhp,teh ; blk>=128: nht
__device__ float g_comb[256][2];  // blk<128: md,le ; blk>=128: s
__device__ unsigned g_ticket;

// ---------------------------------------------------------------------------
__device__ __forceinline__ ull fma2(ull a, ull b, ull c) {
    ull d;
    asm("fma.rn.f32x2 %0, %1, %2, %3;" : "=l"(d) : "l"(a), "l"(b), "l"(c));
    return d;
}
__device__ __forceinline__ ull dup2(float x) {
    ull d;
    asm("mov.b64 %0, {%1, %1};" : "=l"(d) : "f"(x));
    return d;
}
__device__ __forceinline__ float2 unpack2(ull v) {
    float2 r;
    asm("mov.b64 {%0, %1}, %2;" : "=f"(r.x), "=f"(r.y) : "l"(v));
    return r;
}
// smaller float -> larger unsigned key (monotone inverted)
__device__ __forceinline__ unsigned encM(float f) {
    unsigned u = __float_as_uint(f);
    return ~(u ^ ((unsigned)((int)u >> 31) | 0x80000000u));
}
__device__ __forceinline__ float decM(unsigned key, unsigned& raw) {
    unsigned enc = ~key;
    unsigned m = (enc & 0x80000000u) ? 0x80000000u : 0xFFFFFFFFu;
    raw = enc ^ m;
    return __uint_as_float(raw);
}

__device__ __forceinline__ float blockReduceSum(float v, float* sh) {
    const unsigned full = 0xffffffffu;
    #pragma unroll
    for (int o = 16; o > 0; o >>= 1) v += __shfl_down_sync(full, v, o);
    int w = threadIdx.x >> 5, l = threadIdx.x & 31;
    __syncthreads();
    if (l == 0) sh[w] = v;
    __syncthreads();
    if (threadIdx.x < 32) {
        v = (threadIdx.x < (blockDim.x >> 5)) ? sh[threadIdx.x] : 0.0f;
        #pragma unroll
        for (int o = 16; o > 0; o >>= 1) v += __shfl_down_sync(full, v, o);
    }
    return v;
}

// ---------------------------------------------------------------------------
// Data transform + cheap reductions. 256 blocks:
//   [0,128)  pred side (b=blk>>2, seg=blk&3): pack + ent/kld/nhp/teh
//   [128,256) tgt side: pack + nht
__global__ __launch_bounds__(256) void prep_kernel(
    const float* __restrict__ preds, const float* __restrict__ target,
    const float* __restrict__ mask,  const float* __restrict__ mu,
    const float* __restrict__ logvar) {
    __shared__ float shr[8];
    int blk = blockIdx.x, tid = threadIdx.x;

    if (blk < 128) {
        int b = blk >> 2, seg = blk & 3;
        int jp = seg * 256 + tid;
        int n = 2 * jp;
        const float* pb = preds + (size_t)b * 5 * NPTS;
        float2 x = *(const float2*)(pb + n);
        float2 y = *(const float2*)(pb + NPTS + n);
        float2 z = *(const float2*)(pb + 2 * NPTS + n);
        float2 E = *(const float2*)(pb + 3 * NPTS + n);
        float2 h = *(const float2*)(pb + 4 * NPTS + n);
        float pn0 = x.x * x.x + y.x * y.x + z.x * z.x;
        float pn1 = x.y * x.y + y.y * y.y + z.y * z.y;
        g_predPA[b * 1024 + jp] = make_float4(-2.f * x.x, -2.f * x.y, -2.f * y.x, -2.f * y.y);
        g_predPB[b * 1024 + jp] = make_float4(-2.f * z.x, -2.f * z.y, pn0, pn1);
        g_predS[b * NPTS + n]     = make_float4(-2.f * x.x, -2.f * y.x, -2.f * z.x, pn0);
        g_predS[b * NPTS + n + 1] = make_float4(-2.f * x.y, -2.f * y.y, -2.f * z.y, pn1);
        float nhp = h.x + h.y;
        float teh = E.x * h.x + E.y * h.y;
        float ent = -(h.x * __logf(h.x + EPSF) + (1.f - h.x) * __logf(1.f - h.x + EPSF))
                    -(h.y * __logf(h.y + EPSF) + (1.f - h.y) * __logf(1.f - h.y + EPSF));
        float kld = 0.f;
        if (tid < 64) {
            int ki = blk * 64 + tid;    // 128 x 64 = 8192 = B_*L_
            float m_ = mu[ki], lv = logvar[ki];
            kld = 1.f + lv - m_ * m_ - __expf(lv);
        }
        ent = blockReduceSum(ent, shr);
        kld = blockReduceSum(kld, shr);
        nhp = blockReduceSum(nhp, shr);
        teh = blockReduceSum(teh, shr);
        if (tid == 0) {
            float* s = g_prep[blk];
            s[0] = ent; s[1] = kld; s[2] = nhp; s[3] = teh;
        }
    } else {
        int w = blk - 128;
        int b = w >> 2, seg = w & 3;
        int jp = seg * 256 + tid;
        int n = 2 * jp;
        const float* tb = target + (size_t)b * 4 * NPTS;
        float2 x = *(const float2*)(tb + n);
        float2 y = *(const float2*)(tb + NPTS + n);
        float2 z = *(const float2*)(tb + 2 * NPTS + n);
        float2 mk = *(const float2*)(mask + b * NPTS + n);
        float tn0 = x.x * x.x + y.x * y.x + z.x * z.x;
        float tn1 = x.y * x.y + y.y * y.y + z.y * z.y;
        g_tgtPA[b * 1024 + jp] = make_float4(x.x, x.y, y.x, y.y);
        g_tgtPB[b * 1024 + jp] = make_float4(z.x, z.y,
                                             tn0 + (mk.x == 0.f ? BIGF : 0.f),
                                             tn1 + (mk.y == 0.f ? BIGF : 0.f));
        g_tgtS[b * NPTS + n]     = make_float4(x.x, y.x, z.x, tn0);
        g_tgtS[b * NPTS + n + 1] = make_float4(x.y, y.y, z.y, tn1);
        float nht = blockReduceSum(mk.x + mk.y, shr);
        if (tid == 0) g_prep[blk][0] = nht;
    }
}

// ---------------------------------------------------------------------------
// Chamfer (R4 measured-best core, init-free keys). 1024 blocks:
//   [0,512)   pass1: pred->tgt, argmin in low 11 mantissa bits
//   [512,1024) pass2: tgt->pred, plain min
// Each block: 2048 register points (8/thread) x one 128-point smem chunk.
__global__ __launch_bounds__(256, 2) void chamfer_kernel() {
    __shared__ ulonglong2 shA[64], shB[64];
    int blk = blockIdx.x, tid = threadIdx.x;
    bool isP1 = blk < 512;
    int w = isP1 ? blk : blk - 512;
    int b = w >> 4, chunk = w & 15;

    if (tid < 64) {
        const float4* PA = isP1 ? g_tgtPA : g_predPA;
        const float4* PB = isP1 ? g_tgtPB : g_predPB;
        float4 a = PA[b * 1024 + chunk * 64 + tid];
        float4 v = PB[b * 1024 + chunk * 64 + tid];
        shA[tid] = *(ulonglong2*)&a;
        shB[tid] = *(ulonglong2*)&v;
    }
    __syncthreads();

    if (isP1) {
        int pbase = b * NPTS + tid;
        ull ax2[8], ay2[8], az2[8];
        #pragma unroll
        for (int i = 0; i < 8; i++) {
            float4 p = g_predS[pbase + i * 256];
            ax2[i] = dup2(p.x); ay2[i] = dup2(p.y); az2[i] = dup2(p.z);
        }
        float bl[8], bh[8];
        #pragma unroll
        for (int i = 0; i < 8; i++) { bl[i] = 3.4e38f; bh[i] = 3.4e38f; }

        unsigned jlo = (unsigned)(chunk * 128);
        #pragma unroll 4
        for (int j = 0; j < 64; j++) {
            ulonglong2 A = shA[j], Bv = shB[j];
            unsigned jhi = jlo | 1u;
            #pragma unroll
            for (int i = 0; i < 8; i++) {
                ull t = fma2(az2[i], Bv.x, Bv.y);
                t = fma2(ay2[i], A.y, t);
                t = fma2(ax2[i], A.x, t);
                float2 v = unpack2(t);
                unsigned elo = (__float_as_uint(v.x) & 0xFFFFF800u) | jlo;
                unsigned ehi = (__float_as_uint(v.y) & 0xFFFFF800u) | jhi;
                bl[i] = fminf(bl[i], __uint_as_float(elo));
                bh[i] = fminf(bh[i], __uint_as_float(ehi));
            }
            jlo += 2;
        }
        #pragma unroll
        for (int i = 0; i < 8; i++)
            atomicMax(&g_min1[pbase + i * 256], encM(fminf(bl[i], bh[i])));
    } else {
        int tbase = b * NPTS + tid;
        ull tx2[8], ty2[8], tz2[8];
        #pragma unroll
        for (int i = 0; i < 8; i++) {
            float4 t = g_tgtS[tbase + i * 256];
            tx2[i] = dup2(t.x); ty2[i] = dup2(t.y); tz2[i] = dup2(t.z);
        }
        float bl[8], bh[8];
        #pragma unroll
        for (int i = 0; i < 8; i++) { bl[i] = 3.4e38f; bh[i] = 3.4e38f; }

        #pragma unroll 4
        for (int j = 0; j < 64; j++) {
            ulonglong2 A = shA[j], Bv = shB[j];
            #pragma unroll
            for (int i = 0; i < 8; i++) {
                ull t = fma2(tz2[i], Bv.x, Bv.y);
                t = fma2(ty2[i], A.y, t);
                t = fma2(tx2[i], A.x, t);
                float2 v = unpack2(t);
                bl[i] = fminf(bl[i], v.x);
                bh[i] = fminf(bh[i], v.y);
            }
        }
        #pragma unroll
        for (int i = 0; i < 8; i++)
            atomicMax(&g_min2[tbase + i * 256], encM(fminf(bl[i], bh[i])));
    }
}

// ---------------------------------------------------------------------------
// Lean combine + ticketed finalize. 256 blocks, 512 points each:
//   [0,128)  pred side: minD_pred, |dE|
//   [128,256) tgt side: minD_tgt*mask
__global__ __launch_bounds__(256) void combine_kernel(
    const float* __restrict__ preds, const float* __restrict__ target,
    const float* __restrict__ mask,  const float* __restrict__ e_init,
    const float* __restrict__ kl_weight, float* __restrict__ out, int out_size) {
    __shared__ float shr[8];
    __shared__ int s_last;
    int blk = blockIdx.x, tid = threadIdx.x;

    if (blk < 128) {
        int b = blk >> 2, seg = blk & 3;
        const float* pb = preds + (size_t)b * 5 * NPTS;
        const float* tE = target + (size_t)b * 4 * NPTS + 3 * NPTS;
        float md = 0.f, le = 0.f;
        #pragma unroll
        for (int r = 0; r < 2; r++) {
            int n = seg * 512 + r * 256 + tid;
            int gidx = b * NPTS + n;
            unsigned raw;
            float best = decM(g_min1[gidx], raw);
            g_min1[gidx] = 0u;
            int idx = (int)(raw & 0x7FFu);
            md += fmaxf(g_predS[gidx].w + best, 0.f);
            le += fabsf(pb[3 * NPTS + n] - tE[idx]);
        }
        md = blockReduceSum(md, shr);
        le = blockReduceSum(le, shr);
        if (tid == 0) { g_comb[blk][0] = md; g_comb[blk][1] = le; }
    } else {
        int w = blk - 128;
        int b = w >> 2, seg = w & 3;
        float s = 0.f;
        #pragma unroll
        for (int r = 0; r < 2; r++) {
            int m = seg * 512 + r * 256 + tid;
            int gidx = b * NPTS + m;
            unsigned raw;
            float best = decM(g_min2[gidx], raw);
            g_min2[gidx] = 0u;
            s += fmaxf(g_tgtS[gidx].w + best, 0.f) * mask[gidx];
        }
        s = blockReduceSum(s, shr);
        if (tid == 0) g_comb[blk][0] = s;
    }

    if (tid == 0) {
        __threadfence();
        unsigned t = atomicAdd(&g_ticket, 1u);
        s_last = (t == 255u);
    }
    __syncthreads();
    if (!s_last) return;

    // ---- last block: aggregate + finalize ----
    float vMD = blockReduceSum(tid < 128 ? g_comb[tid][0] : 0.f, shr);
    float vLE = blockReduceSum(tid < 128 ? g_comb[tid][1] : 0.f, shr);
    float vS  = blockReduceSum(tid >= 128 ? g_comb[tid][0] : 0.f, shr);
    float vEN = blockReduceSum(tid < 128 ? g_prep[tid][0] : 0.f, shr);
    float vKL = blockReduceSum(tid < 128 ? g_prep[tid][1] : 0.f, shr);
    float vNH = blockReduceSum(tid >= 128 ? g_prep[tid][0] : 0.f, shr);

    float dh2 = 0.f, de2 = 0.f;
    if (tid < B_) {
        float nhp = 0.f, teh = 0.f, nht = 0.f;
        #pragma unroll
        for (int s2 = 0; s2 < 4; s2++) {
            nhp += g_prep[4 * tid + s2][2];
            teh += g_prep[4 * tid + s2][3];
            nht += g_prep[128 + 4 * tid + s2][0];
        }
        float dh = nhp - nht;
        float de = teh - e_init[tid];
        dh2 = dh * dh; de2 = de * de;
    }
    if (tid < 32) {
        const unsigned full = 0xffffffffu;
        #pragma unroll
        for (int o = 16; o > 0; o >>= 1) {
            dh2 += __shfl_down_sync(full, dh2, o);
            de2 += __shfl_down_sync(full, de2, o);
        }
    }
    if (tid == 0) {
        float chamP = vMD / (float)(B_ * NPTS);
        float chamT = vS / vNH;
        float loss_chamf = (chamT + chamP) * LAMBDA_CHAMFER;
        float localE = vLE / (float)(B_ * NPTS);
        float ge   = LAMBDA_E_SUM * de2 / (float)B_;
        float hit  = LAMBDA_HIT   * dh2 / (float)B_;
        float entr = LAMBDA_HIT_ENTROPY * vEN / (float)(B_ * NPTS);
        float kl   = kl_weight[0] * (-0.5f * vKL / (float)B_);
        float total = loss_chamf + localE + kl + ge + hit + entr;

        if (out_size >= 6) {
            out[0] = total;
            out[1] = loss_chamf;
            out[2] = localE;
            out[3] = ge;
            out[4] = hit;
            out[5] = kl;
        } else if (out_size == 5) {
            out[0] = loss_chamf; out[1] = localE; out[2] = ge;
            out[3] = hit;        out[4] = kl;
        } else {
            out[0] = total;
        }
        g_ticket = 0u;   // reset for next graph replay
    }
}

// ---------------------------------------------------------------------------
extern "C" void kernel_launch(void* const* d_in, const int* in_sizes, int n_in,
                              void* d_out, int out_size) {
    const float* preds  = (const float*)d_in[0];
    const float* target = (const float*)d_in[1];
    const float* tmask  = (const float*)d_in[2];
    const float* mu     = (const float*)d_in[3];
    const float* logvar = (const float*)d_in[4];
    const float* e_init = (const float*)d_in[5];
    const float* klw    = (const float*)d_in[6];
    float* out = (float*)d_out;

    prep_kernel<<<256, 256>>>(preds, target, tmask, mu, logvar);
    chamfer_kernel<<<1024, 256>>>();
    combine_kernel<<<256, 256>>>(preds, target, tmask, e_init, klw, out, out_size);
}